// round 5
// baseline (speedup 1.0000x reference)
#include <cuda_runtime.h>
#include <cstdint>

#define T_STEPS 5
#define NN 100000
#define DD 64
#define EE 400000

#define M_TOT (T_STEPS * NN)            // 500000 (t,node) rows
#define CHUNK 1024
#define NCHUNK ((M_TOT + CHUNK - 1) / CHUNK)  // 489

typedef unsigned long long u64;

// ---------------- device scratch (static globals: allocation-free) ----------
__device__ float g_A[(size_t)T_STEPS * NN * DD];   // x @ W_top  (128 MB)
__device__ float g_B[(size_t)T_STEPS * NN * DD];   // x @ W_bot  (128 MB)
__device__ int   g_cnt[M_TOT];
__device__ int   g_rowptr[M_TOT];
__device__ int   g_cursor[M_TOT];
__device__ int   g_sdst[(size_t)T_STEPS * EE];     // dst sorted by (t,src)
__device__ int   g_chunksum[NCHUNK];
__device__ int   g_chunkoff[NCHUNK];
__device__ float g_w[T_STEPS];

// ---------------- packed f32x2 helpers (Blackwell full-rate fp32 path) ------
__device__ __forceinline__ u64 pack2(float lo, float hi) {
    u64 r;
    asm("mov.b64 %0, {%1, %2};" : "=l"(r) : "f"(lo), "f"(hi));
    return r;
}
__device__ __forceinline__ u64 ffma2(u64 a, u64 b, u64 c) {
    u64 r;
    asm("fma.rn.f32x2 %0, %1, %2, %3;" : "=l"(r) : "l"(a), "l"(b), "l"(c));
    return r;
}

// ---------------- tiny kernels ---------------------------------------------
__global__ void k_zero_cnt() {
    int i = blockIdx.x * blockDim.x + threadIdx.x;
    if (i < M_TOT) g_cnt[i] = 0;
}

__global__ void k_softmax(const float* __restrict__ ea) {
    if (threadIdx.x == 0) {
        float m = ea[0];
        for (int t = 1; t < T_STEPS; t++) m = fmaxf(m, ea[t]);
        float s = 0.f, e[T_STEPS];
        for (int t = 0; t < T_STEPS; t++) { e[t] = __expf(ea[t] - m); s += e[t]; }
        for (int t = 0; t < T_STEPS; t++) g_w[t] = e[t] / s;
    }
}

__global__ void k_hist(const int* __restrict__ edges) {
    int i = blockIdx.x * blockDim.x + threadIdx.x;
    if (i >= T_STEPS * EE) return;
    int t = i / EE, e = i - t * EE;
    int src = edges[(size_t)t * 2 * EE + e];
    atomicAdd(&g_cnt[t * NN + src], 1);
}

__global__ void k_scan1() {
    __shared__ int sh[256];
    int c = blockIdx.x, tid = threadIdx.x;
    int base = c * CHUNK;
    int s = 0;
    #pragma unroll
    for (int i = 0; i < CHUNK / 256; i++) {
        int idx = base + i * 256 + tid;
        if (idx < M_TOT) s += g_cnt[idx];
    }
    sh[tid] = s; __syncthreads();
    for (int off = 128; off > 0; off >>= 1) {
        if (tid < off) sh[tid] += sh[tid + off];
        __syncthreads();
    }
    if (tid == 0) g_chunksum[c] = sh[0];
}

__global__ void k_scan2() {
    if (threadIdx.x == 0) {
        int run = 0;
        for (int c = 0; c < NCHUNK; c++) { g_chunkoff[c] = run; run += g_chunksum[c]; }
    }
}

__global__ void k_scan3() {
    __shared__ int sh[256];
    int c = blockIdx.x, tid = threadIdx.x;
    const int PT = CHUNK / 256;  // 4
    int base = c * CHUNK + tid * PT;
    int v[PT];
    int s = 0;
    #pragma unroll
    for (int i = 0; i < PT; i++) {
        int idx = base + i;
        int cv = (idx < M_TOT) ? g_cnt[idx] : 0;
        v[i] = s; s += cv;
    }
    sh[tid] = s; __syncthreads();
    // inclusive Hillis-Steele
    for (int off = 1; off < 256; off <<= 1) {
        int add = (tid >= off) ? sh[tid - off] : 0;
        __syncthreads();
        sh[tid] += add;
        __syncthreads();
    }
    int texcl = ((tid > 0) ? sh[tid - 1] : 0) + g_chunkoff[c];
    #pragma unroll
    for (int i = 0; i < PT; i++) {
        int idx = base + i;
        if (idx < M_TOT) {
            int o = texcl + v[i];
            g_rowptr[idx] = o;
            g_cursor[idx] = o;
        }
    }
}

__global__ void k_scatter(const int* __restrict__ edges) {
    int i = blockIdx.x * blockDim.x + threadIdx.x;
    if (i >= T_STEPS * EE) return;
    int t = i / EE, e = i - t * EE;
    int src = edges[(size_t)t * 2 * EE + e];
    int dst = edges[(size_t)t * 2 * EE + EE + e];
    int pos = atomicAdd(&g_cursor[t * NN + src], 1);
    g_sdst[pos] = dst;
}

// ---------------- GEMM: A[t] = x @ W[t][0:64,:], B[t] = x @ W[t][64:128,:] --
// Block tile: 128 nodes x 128 outputs (j<64 -> A, j>=64 -> B), k = 64 (full).
// Inner loop uses packed fma.rn.f32x2 (FFMA2): 32 packed FMAs per k instead of
// 64 scalar FFMA -> 2x fp32 pipe throughput on sm_103a (scalar FFMA is rt=2).
#define XS_STRIDE 132
__global__ void __launch_bounds__(256, 2) k_gemm(const float* __restrict__ x,
                                                 const float* __restrict__ W) {
    extern __shared__ float smem[];
    float* ws = smem;              // [64][128]
    float* xs = smem + 64 * 128;   // [64][XS_STRIDE] transposed x tile

    int t  = blockIdx.y;
    int n0 = blockIdx.x * 128;
    int tid = threadIdx.x;
    const float* Wt = W + (size_t)t * 128 * 64;

    for (int i = tid; i < 64 * 128; i += 256) {
        int k = i >> 7, j = i & 127;
        ws[i] = Wt[(k + ((j >> 6) << 6)) * 64 + (j & 63)];
    }
    for (int i = tid; i < 128 * 64; i += 256) {
        int nl = i >> 6, k = i & 63;
        int n = n0 + nl;
        xs[k * XS_STRIDE + nl] = (n < NN) ? x[(size_t)n * 64 + k] : 0.f;
    }
    __syncthreads();

    int jc = tid & 15, nr = tid >> 4;
    int j0 = jc * 4, nl0 = nr * 4;

    // acc[a][p]: a = node micro-row (0..7), p = packed output pair (b=2p,2p+1)
    u64 acc[8][4];
    #pragma unroll
    for (int a = 0; a < 8; a++)
        #pragma unroll
        for (int p = 0; p < 4; p++) acc[a][p] = 0ull;

    #pragma unroll 4
    for (int k = 0; k < 64; k++) {
        float4 xv0 = *(const float4*)&xs[k * XS_STRIDE + nl0];
        float4 xv1 = *(const float4*)&xs[k * XS_STRIDE + 64 + nl0];
        // W pairs load directly as 64-bit packed values (natural f32x2 pairs)
        ulonglong2 w0 = *(const ulonglong2*)&ws[k * 128 + j0];
        ulonglong2 w1 = *(const ulonglong2*)&ws[k * 128 + 64 + j0];
        u64 wp[4] = {w0.x, w0.y, w1.x, w1.y};
        u64 xb[8];
        xb[0] = pack2(xv0.x, xv0.x); xb[1] = pack2(xv0.y, xv0.y);
        xb[2] = pack2(xv0.z, xv0.z); xb[3] = pack2(xv0.w, xv0.w);
        xb[4] = pack2(xv1.x, xv1.x); xb[5] = pack2(xv1.y, xv1.y);
        xb[6] = pack2(xv1.z, xv1.z); xb[7] = pack2(xv1.w, xv1.w);
        #pragma unroll
        for (int a = 0; a < 8; a++)
            #pragma unroll
            for (int p = 0; p < 4; p++)
                acc[a][p] = ffma2(xb[a], wp[p], acc[a][p]);
    }

    #pragma unroll
    for (int a = 0; a < 8; a++) {
        int nl = (a < 4) ? (nl0 + a) : (64 + nl0 + (a - 4));
        int n = n0 + nl;
        if (n >= NN) continue;
        size_t rowbase = ((size_t)t * NN + n) * 64;
        // acc[a][0..1] = A outputs j0..j0+3 ; acc[a][2..3] = B outputs j0..j0+3
        ulonglong2 va = make_ulonglong2(acc[a][0], acc[a][1]);
        ulonglong2 vb = make_ulonglong2(acc[a][2], acc[a][3]);
        *(ulonglong2*)&g_A[rowbase + j0] = va;
        *(ulonglong2*)&g_B[rowbase + j0] = vb;
    }
}

// ---------------- finalize: one warp per node, loops t, reduces edges -------
__global__ void k_finalize(const float* __restrict__ bias,
                           float* __restrict__ out) {
    int gw = (blockIdx.x * blockDim.x + threadIdx.x) >> 5;
    int lane = threadIdx.x & 31;
    if (gw >= NN) return;
    int n = gw;

    float ox = 0.f, oy = 0.f;

    for (int t = 0; t < T_STEPS; t++) {
        int row = t * NN + n;
        int beg = g_rowptr[row];
        int cnt = g_cnt[row];
        float2 a  = *(const float2*)&g_A[(size_t)row * 64 + 2 * lane];
        float2 bi = *(const float2*)&bias[t * 64 + 2 * lane];
        float ax = a.x + bi.x, ay = a.y + bi.y;
        const float* Bt = g_B + (size_t)t * NN * 64;

        float sx = 0.f, sy = 0.f;
        for (int base = 0; base < cnt; base += 32) {
            int m = min(32, cnt - base);
            int d = (lane < m) ? g_sdst[beg + base + lane] : 0;
            int i = 0;
            for (; i + 4 <= m; i += 4) {
                int d0 = __shfl_sync(0xffffffffu, d, i);
                int d1 = __shfl_sync(0xffffffffu, d, i + 1);
                int d2 = __shfl_sync(0xffffffffu, d, i + 2);
                int d3 = __shfl_sync(0xffffffffu, d, i + 3);
                float2 b0 = *(const float2*)&Bt[(size_t)d0 * 64 + 2 * lane];
                float2 b1 = *(const float2*)&Bt[(size_t)d1 * 64 + 2 * lane];
                float2 b2 = *(const float2*)&Bt[(size_t)d2 * 64 + 2 * lane];
                float2 b3 = *(const float2*)&Bt[(size_t)d3 * 64 + 2 * lane];
                sx += fmaxf(ax + b0.x, 0.f); sy += fmaxf(ay + b0.y, 0.f);
                sx += fmaxf(ax + b1.x, 0.f); sy += fmaxf(ay + b1.y, 0.f);
                sx += fmaxf(ax + b2.x, 0.f); sy += fmaxf(ay + b2.y, 0.f);
                sx += fmaxf(ax + b3.x, 0.f); sy += fmaxf(ay + b3.y, 0.f);
            }
            for (; i < m; i++) {
                int di = __shfl_sync(0xffffffffu, d, i);
                float2 bv = *(const float2*)&Bt[(size_t)di * 64 + 2 * lane];
                sx += fmaxf(ax + bv.x, 0.f);
                sy += fmaxf(ay + bv.y, 0.f);
            }
        }
        float scale = g_w[t] / (float)max(cnt, 1);
        ox = fmaf(scale, sx, ox);
        oy = fmaf(scale, sy, oy);
    }
    float2 o = make_float2(ox, oy);
    *(float2*)&out[(size_t)n * 64 + 2 * lane] = o;
}

// ---------------- launch ----------------------------------------------------
extern "C" void kernel_launch(void* const* d_in, const int* in_sizes, int n_in,
                              void* d_out, int out_size) {
    const float* x     = (const float*)d_in[0];  // (N, 64)
    const float* W     = (const float*)d_in[1];  // (T, 128, 64)
    const float* bias  = (const float*)d_in[2];  // (T, 64)
    const float* ea    = (const float*)d_in[3];  // (T,)
    const int*   edges = (const int*)d_in[4];    // (T, 2, E)
    float* out = (float*)d_out;

    (void)in_sizes; (void)n_in; (void)out_size;

    k_zero_cnt<<<(M_TOT + 255) / 256, 256>>>();
    k_softmax<<<1, 32>>>(ea);
    k_hist<<<(T_STEPS * EE + 255) / 256, 256>>>(edges);
    k_scan1<<<NCHUNK, 256>>>();
    k_scan2<<<1, 32>>>();
    k_scan3<<<NCHUNK, 256>>>();
    k_scatter<<<(T_STEPS * EE + 255) / 256, 256>>>(edges);

    static int smem_set = 0;
    int gemm_smem = (64 * 128 + 64 * XS_STRIDE) * sizeof(float);  // 66560 B
    if (!smem_set) {
        cudaFuncSetAttribute(k_gemm, cudaFuncAttributeMaxDynamicSharedMemorySize,
                             gemm_smem);
        smem_set = 1;
    }
    dim3 ggrid((NN + 127) / 128, T_STEPS);
    k_gemm<<<ggrid, 256, gemm_smem>>>(x, W);

    k_finalize<<<(NN * 32 + 255) / 256, 256>>>(bias, out);
}

// round 6
// speedup vs baseline: 1.1950x; 1.1950x over previous
#include <cuda_runtime.h>
#include <cstdint>

#define T_STEPS 5
#define NN 100000
#define DD 64
#define EE 400000

#define M_TOT (T_STEPS * NN)            // 500000 (t,node) rows
#define CHUNK 1024
#define NCHUNK ((M_TOT + CHUNK - 1) / CHUNK)  // 489

// ---------------- device scratch (static globals: allocation-free) ----------
__device__ float g_A[(size_t)T_STEPS * NN * DD];   // x @ W_top  (128 MB)
__device__ float g_B[(size_t)T_STEPS * NN * DD];   // x @ W_bot  (128 MB)
__device__ int   g_cnt[M_TOT];
__device__ int   g_rowptr[M_TOT];
__device__ int   g_cursor[M_TOT];
__device__ int   g_sdst[(size_t)T_STEPS * EE];     // dst sorted by (t,src)
__device__ int   g_chunksum[NCHUNK];
__device__ int   g_chunkoff[NCHUNK];
__device__ float g_w[T_STEPS];

// ---------------- tf32 helpers ----------------------------------------------
__device__ __forceinline__ void tf32_split(float v, uint32_t& hi, uint32_t& lo) {
    uint32_t h;
    asm("cvt.rna.tf32.f32 %0, %1;" : "=r"(h) : "f"(v));
    float r = v - __uint_as_float(h);
    uint32_t l;
    asm("cvt.rna.tf32.f32 %0, %1;" : "=r"(l) : "f"(r));
    hi = h; lo = l;
}

__device__ __forceinline__ void mma_tf32(float* c, const uint32_t* a,
                                         uint32_t b0, uint32_t b1) {
    asm("mma.sync.aligned.m16n8k8.row.col.f32.tf32.tf32.f32 "
        "{%0,%1,%2,%3}, {%4,%5,%6,%7}, {%8,%9}, {%0,%1,%2,%3};"
        : "+f"(c[0]), "+f"(c[1]), "+f"(c[2]), "+f"(c[3])
        : "r"(a[0]), "r"(a[1]), "r"(a[2]), "r"(a[3]), "r"(b0), "r"(b1));
}

// ---------------- tiny kernels ---------------------------------------------
__global__ void k_zero_cnt() {
    int i = blockIdx.x * blockDim.x + threadIdx.x;
    if (i < M_TOT) g_cnt[i] = 0;
}

__global__ void k_softmax(const float* __restrict__ ea) {
    if (threadIdx.x == 0) {
        float m = ea[0];
        for (int t = 1; t < T_STEPS; t++) m = fmaxf(m, ea[t]);
        float s = 0.f, e[T_STEPS];
        for (int t = 0; t < T_STEPS; t++) { e[t] = __expf(ea[t] - m); s += e[t]; }
        for (int t = 0; t < T_STEPS; t++) g_w[t] = e[t] / s;
    }
}

__global__ void k_hist(const int* __restrict__ edges) {
    int i = blockIdx.x * blockDim.x + threadIdx.x;
    if (i >= T_STEPS * EE) return;
    int t = i / EE, e = i - t * EE;
    int src = edges[(size_t)t * 2 * EE + e];
    atomicAdd(&g_cnt[t * NN + src], 1);
}

__global__ void k_scan1() {
    __shared__ int sh[256];
    int c = blockIdx.x, tid = threadIdx.x;
    int base = c * CHUNK;
    int s = 0;
    #pragma unroll
    for (int i = 0; i < CHUNK / 256; i++) {
        int idx = base + i * 256 + tid;
        if (idx < M_TOT) s += g_cnt[idx];
    }
    sh[tid] = s; __syncthreads();
    for (int off = 128; off > 0; off >>= 1) {
        if (tid < off) sh[tid] += sh[tid + off];
        __syncthreads();
    }
    if (tid == 0) g_chunksum[c] = sh[0];
}

__global__ void k_scan2() {
    if (threadIdx.x == 0) {
        int run = 0;
        for (int c = 0; c < NCHUNK; c++) { g_chunkoff[c] = run; run += g_chunksum[c]; }
    }
}

__global__ void k_scan3() {
    __shared__ int sh[256];
    int c = blockIdx.x, tid = threadIdx.x;
    const int PT = CHUNK / 256;  // 4
    int base = c * CHUNK + tid * PT;
    int v[PT];
    int s = 0;
    #pragma unroll
    for (int i = 0; i < PT; i++) {
        int idx = base + i;
        int cv = (idx < M_TOT) ? g_cnt[idx] : 0;
        v[i] = s; s += cv;
    }
    sh[tid] = s; __syncthreads();
    for (int off = 1; off < 256; off <<= 1) {
        int add = (tid >= off) ? sh[tid - off] : 0;
        __syncthreads();
        sh[tid] += add;
        __syncthreads();
    }
    int texcl = ((tid > 0) ? sh[tid - 1] : 0) + g_chunkoff[c];
    #pragma unroll
    for (int i = 0; i < PT; i++) {
        int idx = base + i;
        if (idx < M_TOT) {
            int o = texcl + v[i];
            g_rowptr[idx] = o;
            g_cursor[idx] = o;
        }
    }
}

__global__ void k_scatter(const int* __restrict__ edges) {
    int i = blockIdx.x * blockDim.x + threadIdx.x;
    if (i >= T_STEPS * EE) return;
    int t = i / EE, e = i - t * EE;
    int src = edges[(size_t)t * 2 * EE + e];
    int dst = edges[(size_t)t * 2 * EE + EE + e];
    int pos = atomicAdd(&g_cursor[t * NN + src], 1);
    g_sdst[pos] = dst;
}

// ---------------- GEMM via tensor cores (3xTF32, fp32-grade accuracy) -------
// C[128 nodes x 128 j] = X[128 x 64] * Wcat[64 x 128]; j<64 -> g_A, j>=64 -> g_B.
// mma.sync.m16n8k8 tf32, warp grid 4(m) x 2(n): warp tile 32 x 64.
// 3xTF32: X=Xh+Xl, W=Wh+Wl, C ~= Xh*Wh + Xh*Wl + Xl*Wh  (err ~2^-22).
#define XS_STRIDE 68
#define WS_STRIDE 136
__global__ void __launch_bounds__(256) k_gemm(const float* __restrict__ x,
                                              const float* __restrict__ W) {
    extern __shared__ float smem[];
    float* xs = smem;                        // [128][XS_STRIDE]
    float* ws = smem + 128 * XS_STRIDE;      // [64][WS_STRIDE]

    int t   = blockIdx.y;
    int n0  = blockIdx.x * 128;
    int tid = threadIdx.x;
    const float* Wt = W + (size_t)t * 128 * 64;

    // fill X tile: 128 rows x 64 k, float4 (rows 16B-aligned: 68*4=272=17*16)
    #pragma unroll
    for (int j = 0; j < 8; j++) {
        int idx = tid + j * 256;             // 2048 float4s
        int nl = idx >> 4, kq = idx & 15;
        int n = n0 + nl;
        float4 v = (n < NN) ? *(const float4*)&x[(size_t)n * 64 + kq * 4]
                            : make_float4(0.f, 0.f, 0.f, 0.f);
        *(float4*)&xs[nl * XS_STRIDE + kq * 4] = v;
    }
    // fill W tile: ws[k][j] : j<64 -> W[k][j], j>=64 -> W[k+64][j-64]
    #pragma unroll
    for (int j = 0; j < 32; j++) {
        int idx = tid + j * 256;             // 8192 floats
        int k = idx >> 7, jj = idx & 127;
        ws[k * WS_STRIDE + jj] = Wt[(k + ((jj >> 6) << 6)) * 64 + (jj & 63)];
    }
    __syncthreads();

    int wid = tid >> 5, lane = tid & 31;
    int warp_m = wid & 3, warp_n = wid >> 2;
    int g = lane >> 2, tg = lane & 3;

    float acc[2][8][4];
    #pragma unroll
    for (int mf = 0; mf < 2; mf++)
        #pragma unroll
        for (int nf = 0; nf < 8; nf++)
            #pragma unroll
            for (int r = 0; r < 4; r++) acc[mf][nf][r] = 0.f;

    #pragma unroll
    for (int ks = 0; ks < 8; ks++) {
        int kk = ks * 8;
        // A fragments (hi/lo) for both 16-row m-frags
        uint32_t ah[2][4], al[2][4];
        #pragma unroll
        for (int mf = 0; mf < 2; mf++) {
            int rb = warp_m * 32 + mf * 16;
            float a0 = xs[(rb + g)     * XS_STRIDE + kk + tg];
            float a1 = xs[(rb + g + 8) * XS_STRIDE + kk + tg];
            float a2 = xs[(rb + g)     * XS_STRIDE + kk + tg + 4];
            float a3 = xs[(rb + g + 8) * XS_STRIDE + kk + tg + 4];
            tf32_split(a0, ah[mf][0], al[mf][0]);
            tf32_split(a1, ah[mf][1], al[mf][1]);
            tf32_split(a2, ah[mf][2], al[mf][2]);
            tf32_split(a3, ah[mf][3], al[mf][3]);
        }
        #pragma unroll
        for (int nf = 0; nf < 8; nf++) {
            int col = warp_n * 64 + nf * 8 + g;
            float b0 = ws[(kk + tg)     * WS_STRIDE + col];
            float b1 = ws[(kk + tg + 4) * WS_STRIDE + col];
            uint32_t bh0, bl0, bh1, bl1;
            tf32_split(b0, bh0, bl0);
            tf32_split(b1, bh1, bl1);
            #pragma unroll
            for (int mf = 0; mf < 2; mf++) {
                mma_tf32(acc[mf][nf], ah[mf], bh0, bh1);
                mma_tf32(acc[mf][nf], ah[mf], bl0, bl1);
                mma_tf32(acc[mf][nf], al[mf], bh0, bh1);
            }
        }
    }

    // epilogue: warp_n==0 -> g_A cols 0..63 ; warp_n==1 -> g_B cols 0..63
    float* dst = warp_n ? g_B : g_A;
    #pragma unroll
    for (int mf = 0; mf < 2; mf++) {
        int rb = warp_m * 32 + mf * 16;
        int nA = n0 + rb + g;
        int nB = n0 + rb + g + 8;
        #pragma unroll
        for (int nf = 0; nf < 8; nf++) {
            int jc = nf * 8 + 2 * tg;
            if (nA < NN) {
                float2 v = make_float2(acc[mf][nf][0], acc[mf][nf][1]);
                *(float2*)&dst[((size_t)t * NN + nA) * 64 + jc] = v;
            }
            if (nB < NN) {
                float2 v = make_float2(acc[mf][nf][2], acc[mf][nf][3]);
                *(float2*)&dst[((size_t)t * NN + nB) * 64 + jc] = v;
            }
        }
    }
}

// ---------------- finalize: one warp per node, loops t, reduces edges -------
__global__ void k_finalize(const float* __restrict__ bias,
                           float* __restrict__ out) {
    int gw = (blockIdx.x * blockDim.x + threadIdx.x) >> 5;
    int lane = threadIdx.x & 31;
    if (gw >= NN) return;
    int n = gw;

    float ox = 0.f, oy = 0.f;

    for (int t = 0; t < T_STEPS; t++) {
        int row = t * NN + n;
        int beg = g_rowptr[row];
        int cnt = g_cnt[row];
        float2 a  = *(const float2*)&g_A[(size_t)row * 64 + 2 * lane];
        float2 bi = *(const float2*)&bias[t * 64 + 2 * lane];
        float ax = a.x + bi.x, ay = a.y + bi.y;
        const float* Bt = g_B + (size_t)t * NN * 64;

        float sx = 0.f, sy = 0.f;
        for (int base = 0; base < cnt; base += 32) {
            int m = min(32, cnt - base);
            int d = (lane < m) ? g_sdst[beg + base + lane] : 0;
            int i = 0;
            for (; i + 4 <= m; i += 4) {
                int d0 = __shfl_sync(0xffffffffu, d, i);
                int d1 = __shfl_sync(0xffffffffu, d, i + 1);
                int d2 = __shfl_sync(0xffffffffu, d, i + 2);
                int d3 = __shfl_sync(0xffffffffu, d, i + 3);
                float2 b0 = *(const float2*)&Bt[(size_t)d0 * 64 + 2 * lane];
                float2 b1 = *(const float2*)&Bt[(size_t)d1 * 64 + 2 * lane];
                float2 b2 = *(const float2*)&Bt[(size_t)d2 * 64 + 2 * lane];
                float2 b3 = *(const float2*)&Bt[(size_t)d3 * 64 + 2 * lane];
                sx += fmaxf(ax + b0.x, 0.f); sy += fmaxf(ay + b0.y, 0.f);
                sx += fmaxf(ax + b1.x, 0.f); sy += fmaxf(ay + b1.y, 0.f);
                sx += fmaxf(ax + b2.x, 0.f); sy += fmaxf(ay + b2.y, 0.f);
                sx += fmaxf(ax + b3.x, 0.f); sy += fmaxf(ay + b3.y, 0.f);
            }
            for (; i < m; i++) {
                int di = __shfl_sync(0xffffffffu, d, i);
                float2 bv = *(const float2*)&Bt[(size_t)di * 64 + 2 * lane];
                sx += fmaxf(ax + bv.x, 0.f);
                sy += fmaxf(ay + bv.y, 0.f);
            }
        }
        float scale = g_w[t] / (float)max(cnt, 1);
        ox = fmaf(scale, sx, ox);
        oy = fmaf(scale, sy, oy);
    }
    float2 o = make_float2(ox, oy);
    *(float2*)&out[(size_t)n * 64 + 2 * lane] = o;
}

// ---------------- launch ----------------------------------------------------
extern "C" void kernel_launch(void* const* d_in, const int* in_sizes, int n_in,
                              void* d_out, int out_size) {
    const float* x     = (const float*)d_in[0];  // (N, 64)
    const float* W     = (const float*)d_in[1];  // (T, 128, 64)
    const float* bias  = (const float*)d_in[2];  // (T, 64)
    const float* ea    = (const float*)d_in[3];  // (T,)
    const int*   edges = (const int*)d_in[4];    // (T, 2, E)
    float* out = (float*)d_out;

    (void)in_sizes; (void)n_in; (void)out_size;

    k_zero_cnt<<<(M_TOT + 255) / 256, 256>>>();
    k_softmax<<<1, 32>>>(ea);
    k_hist<<<(T_STEPS * EE + 255) / 256, 256>>>(edges);
    k_scan1<<<NCHUNK, 256>>>();
    k_scan2<<<1, 32>>>();
    k_scan3<<<NCHUNK, 256>>>();
    k_scatter<<<(T_STEPS * EE + 255) / 256, 256>>>(edges);

    static int smem_set = 0;
    int gemm_smem = (128 * XS_STRIDE + 64 * WS_STRIDE) * sizeof(float);  // 69632 B
    if (!smem_set) {
        cudaFuncSetAttribute(k_gemm, cudaFuncAttributeMaxDynamicSharedMemorySize,
                             gemm_smem);
        smem_set = 1;
    }
    dim3 ggrid((NN + 127) / 128, T_STEPS);
    k_gemm<<<ggrid, 256, gemm_smem>>>(x, W);

    k_finalize<<<(NN * 32 + 255) / 256, 256>>>(bias, out);
}

// round 8
// speedup vs baseline: 1.2001x; 1.0043x over previous
#include <cuda_runtime.h>
#include <cuda_bf16.h>
#include <cstdint>

#define T_STEPS 5
#define NN 100000
#define DD 64
#define EE 400000

#define M_TOT (T_STEPS * NN)            // 500000 (t,node) rows
#define CHUNK 1024
#define NCHUNK ((M_TOT + CHUNK - 1) / CHUNK)  // 489

// ---------------- device scratch (static globals: allocation-free) ----------
__device__ float g_A[(size_t)T_STEPS * NN * DD];   // x @ W_top  (128 MB)
__device__ float g_B[(size_t)T_STEPS * NN * DD];   // x @ W_bot  (128 MB)
__device__ __nv_bfloat16 g_xh[(size_t)NN * DD];    // x hi split (12.8 MB)
__device__ __nv_bfloat16 g_xl[(size_t)NN * DD];    // x lo split
__device__ __nv_bfloat16 g_wh[(size_t)T_STEPS * 128 * 64];  // W hi, [t][j][k]
__device__ __nv_bfloat16 g_wl[(size_t)T_STEPS * 128 * 64];  // W lo, [t][j][k]
__device__ int   g_cnt[M_TOT];
__device__ int   g_rowptr[M_TOT];
__device__ int   g_cursor[M_TOT];
__device__ int   g_sdst[(size_t)T_STEPS * EE];     // dst sorted by (t,src)
__device__ int   g_chunksum[NCHUNK];
__device__ int   g_chunkoff[NCHUNK];
__device__ float g_w[T_STEPS];

// ---------------- helpers ----------------------------------------------------
__device__ __forceinline__ uint32_t pack_bf2(__nv_bfloat16 a, __nv_bfloat16 b) {
    __nv_bfloat162 p = __halves2bfloat162(a, b);
    return *(uint32_t*)&p;
}

__device__ __forceinline__ void mma_bf16(float* c, const uint32_t* a,
                                         uint32_t b0, uint32_t b1) {
    asm("mma.sync.aligned.m16n8k16.row.col.f32.bf16.bf16.f32 "
        "{%0,%1,%2,%3}, {%4,%5,%6,%7}, {%8,%9}, {%0,%1,%2,%3};"
        : "+f"(c[0]), "+f"(c[1]), "+f"(c[2]), "+f"(c[3])
        : "r"(a[0]), "r"(a[1]), "r"(a[2]), "r"(a[3]), "r"(b0), "r"(b1));
}

// ---------------- split kernels ---------------------------------------------
__global__ void k_split_x(const float* __restrict__ x) {
    int i = blockIdx.x * blockDim.x + threadIdx.x;
    if (i >= NN * DD / 4) return;
    float4 v = ((const float4*)x)[i];
    __nv_bfloat16 h0 = __float2bfloat16(v.x);
    __nv_bfloat16 h1 = __float2bfloat16(v.y);
    __nv_bfloat16 h2 = __float2bfloat16(v.z);
    __nv_bfloat16 h3 = __float2bfloat16(v.w);
    __nv_bfloat16 l0 = __float2bfloat16(v.x - __bfloat162float(h0));
    __nv_bfloat16 l1 = __float2bfloat16(v.y - __bfloat162float(h1));
    __nv_bfloat16 l2 = __float2bfloat16(v.z - __bfloat162float(h2));
    __nv_bfloat16 l3 = __float2bfloat16(v.w - __bfloat162float(h3));
    uint2 hv = make_uint2(pack_bf2(h0, h1), pack_bf2(h2, h3));
    uint2 lv = make_uint2(pack_bf2(l0, l1), pack_bf2(l2, l3));
    ((uint2*)g_xh)[i] = hv;
    ((uint2*)g_xl)[i] = lv;
}

// W input: [t][128 kcat][64 jj].  Output (transposed, cat on j):
// g_wh[t][j][k], j in 0..127 (j<64 -> A half, j>=64 -> B half), k in 0..63.
__global__ void k_split_w(const float* __restrict__ W) {
    int i = blockIdx.x * blockDim.x + threadIdx.x;
    if (i >= T_STEPS * 128 * 64) return;
    int t = i >> 13;
    int j = (i >> 6) & 127;
    int k = i & 63;
    int kcat = k + ((j >> 6) << 6);
    float v = W[(size_t)t * 8192 + kcat * 64 + (j & 63)];
    __nv_bfloat16 h = __float2bfloat16(v);
    __nv_bfloat16 l = __float2bfloat16(v - __bfloat162float(h));
    g_wh[i] = h;
    g_wl[i] = l;
}

// ---------------- tiny kernels ---------------------------------------------
__global__ void k_zero_cnt() {
    int i = blockIdx.x * blockDim.x + threadIdx.x;
    if (i < M_TOT) g_cnt[i] = 0;
}

__global__ void k_softmax(const float* __restrict__ ea) {
    if (threadIdx.x == 0) {
        float m = ea[0];
        for (int t = 1; t < T_STEPS; t++) m = fmaxf(m, ea[t]);
        float s = 0.f, e[T_STEPS];
        for (int t = 0; t < T_STEPS; t++) { e[t] = __expf(ea[t] - m); s += e[t]; }
        for (int t = 0; t < T_STEPS; t++) g_w[t] = e[t] / s;
    }
}

__global__ void k_hist(const int* __restrict__ edges) {
    int i = blockIdx.x * blockDim.x + threadIdx.x;
    if (i >= T_STEPS * EE) return;
    int t = i / EE, e = i - t * EE;
    int src = edges[(size_t)t * 2 * EE + e];
    atomicAdd(&g_cnt[t * NN + src], 1);
}

__global__ void k_scan1() {
    __shared__ int sh[256];
    int c = blockIdx.x, tid = threadIdx.x;
    int base = c * CHUNK;
    int s = 0;
    #pragma unroll
    for (int i = 0; i < CHUNK / 256; i++) {
        int idx = base + i * 256 + tid;
        if (idx < M_TOT) s += g_cnt[idx];
    }
    sh[tid] = s; __syncthreads();
    for (int off = 128; off > 0; off >>= 1) {
        if (tid < off) sh[tid] += sh[tid + off];
        __syncthreads();
    }
    if (tid == 0) g_chunksum[c] = sh[0];
}

__global__ void k_scan2() {
    if (threadIdx.x == 0) {
        int run = 0;
        for (int c = 0; c < NCHUNK; c++) { g_chunkoff[c] = run; run += g_chunksum[c]; }
    }
}

__global__ void k_scan3() {
    __shared__ int sh[256];
    int c = blockIdx.x, tid = threadIdx.x;
    const int PT = CHUNK / 256;  // 4
    int base = c * CHUNK + tid * PT;
    int v[PT];
    int s = 0;
    #pragma unroll
    for (int i = 0; i < PT; i++) {
        int idx = base + i;
        int cv = (idx < M_TOT) ? g_cnt[idx] : 0;
        v[i] = s; s += cv;
    }
    sh[tid] = s; __syncthreads();
    for (int off = 1; off < 256; off <<= 1) {
        int add = (tid >= off) ? sh[tid - off] : 0;
        __syncthreads();
        sh[tid] += add;
        __syncthreads();
    }
    int texcl = ((tid > 0) ? sh[tid - 1] : 0) + g_chunkoff[c];
    #pragma unroll
    for (int i = 0; i < PT; i++) {
        int idx = base + i;
        if (idx < M_TOT) {
            int o = texcl + v[i];
            g_rowptr[idx] = o;
            g_cursor[idx] = o;
        }
    }
}

__global__ void k_scatter(const int* __restrict__ edges) {
    int i = blockIdx.x * blockDim.x + threadIdx.x;
    if (i >= T_STEPS * EE) return;
    int t = i / EE, e = i - t * EE;
    int src = edges[(size_t)t * 2 * EE + e];
    int dst = edges[(size_t)t * 2 * EE + EE + e];
    int pos = atomicAdd(&g_cursor[t * NN + src], 1);
    g_sdst[pos] = dst;
}

// ---------------- GEMM via split-bf16 tensor cores --------------------------
// C[128 n x 128 j] = X[128 x 64] * Wcat[64 x 128]; j<64 -> g_A, j>=64 -> g_B.
// X = Xh + Xl, W = Wh + Wl (bf16 splits, precomputed):
//   C ~= Xh*Wh + Xh*Wl + Xl*Wh   (dropped Xl*Wl ~ 2^-16 relative)
// mma.sync.m16n8k16.bf16, warp grid 4(m) x 2(n): warp tile 32 x 64.
// SMEM: 4 tiles [128][72 bf16] (stride 72 -> 144B rows, conflict-free frags).
#define BS 72
__global__ void __launch_bounds__(256) k_gemm() {
    extern __shared__ __nv_bfloat16 smem[];
    __nv_bfloat16* xh_s = smem;                  // [128][BS]
    __nv_bfloat16* xl_s = smem + 128 * BS;
    __nv_bfloat16* wh_s = smem + 2 * 128 * BS;   // [128 j][BS k]
    __nv_bfloat16* wl_s = smem + 3 * 128 * BS;

    int t   = blockIdx.y;
    int n0  = blockIdx.x * 128;
    int tid = threadIdx.x;

    // fill X tiles: 128 rows x 64 bf16 each = 1024 uint4 per array
    #pragma unroll
    for (int j = 0; j < 4; j++) {
        int idx = tid + j * 256;
        int nl = idx >> 3, kq = idx & 7;         // 8 uint4 per row
        int n = n0 + nl;
        uint4 hv = make_uint4(0, 0, 0, 0), lv = make_uint4(0, 0, 0, 0);
        if (n < NN) {
            hv = ((const uint4*)g_xh)[((size_t)n * 64 >> 3) + kq];
            lv = ((const uint4*)g_xl)[((size_t)n * 64 >> 3) + kq];
        }
        ((uint4*)xh_s)[nl * 9 + kq] = hv;        // BS*2/16 = 9 uint4 per row
        ((uint4*)xl_s)[nl * 9 + kq] = lv;
    }
    // fill W tiles: [128 j][64 k] contiguous in g_wh[t]
    const uint4* whg = (const uint4*)(g_wh + (size_t)t * 8192);
    const uint4* wlg = (const uint4*)(g_wl + (size_t)t * 8192);
    #pragma unroll
    for (int j = 0; j < 4; j++) {
        int idx = tid + j * 256;
        int jr = idx >> 3, kq = idx & 7;
        ((uint4*)wh_s)[jr * 9 + kq] = whg[idx];
        ((uint4*)wl_s)[jr * 9 + kq] = wlg[idx];
    }
    __syncthreads();

    int wid = tid >> 5, lane = tid & 31;
    int warp_m = wid & 3, warp_n = wid >> 2;
    int g = lane >> 2, tg = lane & 3;

    float acc[2][8][4];
    #pragma unroll
    for (int mf = 0; mf < 2; mf++)
        #pragma unroll
        for (int nf = 0; nf < 8; nf++)
            #pragma unroll
            for (int r = 0; r < 4; r++) acc[mf][nf][r] = 0.f;

    #pragma unroll
    for (int ks = 0; ks < 4; ks++) {
        int kk = ks * 16;
        uint32_t ah[2][4], al[2][4];
        #pragma unroll
        for (int mf = 0; mf < 2; mf++) {
            int r0 = warp_m * 32 + mf * 16 + g;
            int k0 = kk + 2 * tg;
            ah[mf][0] = *(const uint32_t*)&xh_s[r0 * BS + k0];
            ah[mf][1] = *(const uint32_t*)&xh_s[(r0 + 8) * BS + k0];
            ah[mf][2] = *(const uint32_t*)&xh_s[r0 * BS + k0 + 8];
            ah[mf][3] = *(const uint32_t*)&xh_s[(r0 + 8) * BS + k0 + 8];
            al[mf][0] = *(const uint32_t*)&xl_s[r0 * BS + k0];
            al[mf][1] = *(const uint32_t*)&xl_s[(r0 + 8) * BS + k0];
            al[mf][2] = *(const uint32_t*)&xl_s[r0 * BS + k0 + 8];
            al[mf][3] = *(const uint32_t*)&xl_s[(r0 + 8) * BS + k0 + 8];
        }
        #pragma unroll
        for (int nf = 0; nf < 8; nf++) {
            int col = warp_n * 64 + nf * 8 + g;
            int k0 = kk + 2 * tg;
            uint32_t bh0 = *(const uint32_t*)&wh_s[col * BS + k0];
            uint32_t bh1 = *(const uint32_t*)&wh_s[col * BS + k0 + 8];
            uint32_t bl0 = *(const uint32_t*)&wl_s[col * BS + k0];
            uint32_t bl1 = *(const uint32_t*)&wl_s[col * BS + k0 + 8];
            #pragma unroll
            for (int mf = 0; mf < 2; mf++) {
                mma_bf16(acc[mf][nf], ah[mf], bh0, bh1);
                mma_bf16(acc[mf][nf], ah[mf], bl0, bl1);
                mma_bf16(acc[mf][nf], al[mf], bh0, bh1);
            }
        }
    }

    // epilogue: warp_n==0 -> g_A cols 0..63 ; warp_n==1 -> g_B cols 0..63
    float* dst = warp_n ? g_B : g_A;
    #pragma unroll
    for (int mf = 0; mf < 2; mf++) {
        int rb = warp_m * 32 + mf * 16;
        int nA = n0 + rb + g;
        int nB = n0 + rb + g + 8;
        #pragma unroll
        for (int nf = 0; nf < 8; nf++) {
            int jc = nf * 8 + 2 * tg;
            if (nA < NN) {
                float2 v = make_float2(acc[mf][nf][0], acc[mf][nf][1]);
                *(float2*)&dst[((size_t)t * NN + nA) * 64 + jc] = v;
            }
            if (nB < NN) {
                float2 v = make_float2(acc[mf][nf][2], acc[mf][nf][3]);
                *(float2*)&dst[((size_t)t * NN + nB) * 64 + jc] = v;
            }
        }
    }
}

// ---------------- finalize: one warp per node, prefetch all t upfront -------
__global__ void k_finalize(const float* __restrict__ bias,
                           float* __restrict__ out) {
    int gw = (blockIdx.x * blockDim.x + threadIdx.x) >> 5;
    int lane = threadIdx.x & 31;
    if (gw >= NN) return;
    int n = gw;

    int beg[T_STEPS], cnt[T_STEPS];
    #pragma unroll
    for (int t = 0; t < T_STEPS; t++) {
        int row = t * NN + n;
        beg[t] = g_rowptr[row];
        cnt[t] = g_cnt[row];
    }
    // prefetch first-32 dst indices and A rows for all t (max MLP)
    int dv[T_STEPS];
    #pragma unroll
    for (int t = 0; t < T_STEPS; t++)
        dv[t] = (lane < cnt[t]) ? g_sdst[beg[t] + lane] : 0;
    float2 av[T_STEPS];
    #pragma unroll
    for (int t = 0; t < T_STEPS; t++)
        av[t] = *(const float2*)&g_A[((size_t)(t * NN + n)) * 64 + 2 * lane];

    float ox = 0.f, oy = 0.f;

    #pragma unroll
    for (int t = 0; t < T_STEPS; t++) {
        float2 bi = *(const float2*)&bias[t * 64 + 2 * lane];
        float ax = av[t].x + bi.x, ay = av[t].y + bi.y;
        const float* Bt = g_B + (size_t)t * NN * 64;

        float sx = 0.f, sy = 0.f;
        int c = cnt[t];
        int m = min(32, c);
        int i = 0;
        for (; i + 4 <= m; i += 4) {
            int d0 = __shfl_sync(0xffffffffu, dv[t], i);
            int d1 = __shfl_sync(0xffffffffu, dv[t], i + 1);
            int d2 = __shfl_sync(0xffffffffu, dv[t], i + 2);
            int d3 = __shfl_sync(0xffffffffu, dv[t], i + 3);
            float2 b0 = *(const float2*)&Bt[(size_t)d0 * 64 + 2 * lane];
            float2 b1 = *(const float2*)&Bt[(size_t)d1 * 64 + 2 * lane];
            float2 b2 = *(const float2*)&Bt[(size_t)d2 * 64 + 2 * lane];
            float2 b3 = *(const float2*)&Bt[(size_t)d3 * 64 + 2 * lane];
            sx += fmaxf(ax + b0.x, 0.f); sy += fmaxf(ay + b0.y, 0.f);
            sx += fmaxf(ax + b1.x, 0.f); sy += fmaxf(ay + b1.y, 0.f);
            sx += fmaxf(ax + b2.x, 0.f); sy += fmaxf(ay + b2.y, 0.f);
            sx += fmaxf(ax + b3.x, 0.f); sy += fmaxf(ay + b3.y, 0.f);
        }
        for (; i < m; i++) {
            int di = __shfl_sync(0xffffffffu, dv[t], i);
            float2 bv = *(const float2*)&Bt[(size_t)di * 64 + 2 * lane];
            sx += fmaxf(ax + bv.x, 0.f);
            sy += fmaxf(ay + bv.y, 0.f);
        }
        // rare tail: nodes with degree > 32 in this t
        for (int base = 32; base < c; base += 32) {
            int mm = min(32, c - base);
            int d = (lane < mm) ? g_sdst[beg[t] + base + lane] : 0;
            int ii = 0;
            for (; ii + 4 <= mm; ii += 4) {
                int d0 = __shfl_sync(0xffffffffu, d, ii);
                int d1 = __shfl_sync(0xffffffffu, d, ii + 1);
                int d2 = __shfl_sync(0xffffffffu, d, ii + 2);
                int d3 = __shfl_sync(0xffffffffu, d, ii + 3);
                float2 b0 = *(const float2*)&Bt[(size_t)d0 * 64 + 2 * lane];
                float2 b1 = *(const float2*)&Bt[(size_t)d1 * 64 + 2 * lane];
                float2 b2 = *(const float2*)&Bt[(size_t)d2 * 64 + 2 * lane];
                float2 b3 = *(const float2*)&Bt[(size_t)d3 * 64 + 2 * lane];
                sx += fmaxf(ax + b0.x, 0.f); sy += fmaxf(ay + b0.y, 0.f);
                sx += fmaxf(ax + b1.x, 0.f); sy += fmaxf(ay + b1.y, 0.f);
                sx += fmaxf(ax + b2.x, 0.f); sy += fmaxf(ay + b2.y, 0.f);
                sx += fmaxf(ax + b3.x, 0.f); sy += fmaxf(ay + b3.y, 0.f);
            }
            for (; ii < mm; ii++) {
                int di = __shfl_sync(0xffffffffu, d, ii);
                float2 bv = *(const float2*)&Bt[(size_t)di * 64 + 2 * lane];
                sx += fmaxf(ax + bv.x, 0.f);
                sy += fmaxf(ay + bv.y, 0.f);
            }
        }
        float scale = g_w[t] / (float)max(c, 1);
        ox = fmaf(scale, sx, ox);
        oy = fmaf(scale, sy, oy);
    }
    float2 o = make_float2(ox, oy);
    *(float2*)&out[(size_t)n * 64 + 2 * lane] = o;
}

// ---------------- launch ----------------------------------------------------
extern "C" void kernel_launch(void* const* d_in, const int* in_sizes, int n_in,
                              void* d_out, int out_size) {
    const float* x     = (const float*)d_in[0];  // (N, 64)
    const float* W     = (const float*)d_in[1];  // (T, 128, 64)
    const float* bias  = (const float*)d_in[2];  // (T, 64)
    const float* ea    = (const float*)d_in[3];  // (T,)
    const int*   edges = (const int*)d_in[4];    // (T, 2, E)
    float* out = (float*)d_out;

    (void)in_sizes; (void)n_in; (void)out_size;

    k_zero_cnt<<<(M_TOT + 255) / 256, 256>>>();
    k_softmax<<<1, 32>>>(ea);
    k_split_x<<<(NN * DD / 4 + 255) / 256, 256>>>(x);
    k_split_w<<<(T_STEPS * 128 * 64 + 255) / 256, 256>>>(W);
    k_hist<<<(T_STEPS * EE + 255) / 256, 256>>>(edges);
    k_scan1<<<NCHUNK, 256>>>();
    k_scan2<<<1, 32>>>();
    k_scan3<<<NCHUNK, 256>>>();
    k_scatter<<<(T_STEPS * EE + 255) / 256, 256>>>(edges);

    static int smem_set = 0;
    int gemm_smem = 4 * 128 * BS * sizeof(__nv_bfloat16);  // 73728 B
    if (!smem_set) {
        cudaFuncSetAttribute(k_gemm, cudaFuncAttributeMaxDynamicSharedMemorySize,
                             gemm_smem);
        smem_set = 1;
    }
    dim3 ggrid((NN + 127) / 128, T_STEPS);
    k_gemm<<<ggrid, 256, gemm_smem>>>();

    k_finalize<<<(NN * 32 + 255) / 256, 256>>>(bias, out);
}

// round 10
// speedup vs baseline: 1.2550x; 1.0457x over previous
#include <cuda_runtime.h>
#include <cuda_bf16.h>
#include <cstdint>

#define T_STEPS 5
#define NN 100000
#define DD 64
#define EE 400000

#define M_TOT (T_STEPS * NN)            // 500000 (t,node) rows
#define CHUNK 1024
#define NCHUNK ((M_TOT + CHUNK - 1) / CHUNK)  // 489

// ---------------- device scratch (static globals: allocation-free) ----------
__device__ float g_A[(size_t)T_STEPS * NN * DD];   // x @ W_top  (128 MB)
__device__ float g_B[(size_t)T_STEPS * NN * DD];   // x @ W_bot  (128 MB)
__device__ __nv_bfloat16 g_xh[(size_t)NN * DD];    // x hi split
__device__ __nv_bfloat16 g_xl[(size_t)NN * DD];    // x lo split
__device__ __nv_bfloat16 g_wh[(size_t)T_STEPS * 128 * 64];  // W hi, [t][j][k]
__device__ __nv_bfloat16 g_wl[(size_t)T_STEPS * 128 * 64];  // W lo, [t][j][k]
__device__ int   g_cnt[M_TOT];
__device__ int   g_rowptr[M_TOT];
__device__ int   g_cursor[M_TOT];
__device__ int   g_sdst[(size_t)T_STEPS * EE];     // dst sorted by (t,src)
__device__ int   g_chunksum[NCHUNK];
__device__ int   g_chunkoff[NCHUNK];
__device__ float g_w[T_STEPS];

// ---------------- helpers ----------------------------------------------------
__device__ __forceinline__ uint32_t pack_bf2(__nv_bfloat16 a, __nv_bfloat16 b) {
    __nv_bfloat162 p = __halves2bfloat162(a, b);
    return *(uint32_t*)&p;
}

__device__ __forceinline__ void mma_bf16(float* c, const uint32_t* a,
                                         uint32_t b0, uint32_t b1) {
    asm("mma.sync.aligned.m16n8k16.row.col.f32.bf16.bf16.f32 "
        "{%0,%1,%2,%3}, {%4,%5,%6,%7}, {%8,%9}, {%0,%1,%2,%3};"
        : "+f"(c[0]), "+f"(c[1]), "+f"(c[2]), "+f"(c[3])
        : "r"(a[0]), "r"(a[1]), "r"(a[2]), "r"(a[3]), "r"(b0), "r"(b1));
}

// ---------------- fused split kernel (x and W halves by block range) --------
#define XSPLIT_BLOCKS 6250   // NN*DD/4 / 256
#define WSPLIT_BLOCKS 160    // T*128*64 / 256
__global__ void k_split_xw(const float* __restrict__ x,
                           const float* __restrict__ W) {
    int b = blockIdx.x;
    if (b < XSPLIT_BLOCKS) {
        int i = b * 256 + threadIdx.x;
        if (i >= NN * DD / 4) return;
        float4 v = ((const float4*)x)[i];
        __nv_bfloat16 h0 = __float2bfloat16(v.x);
        __nv_bfloat16 h1 = __float2bfloat16(v.y);
        __nv_bfloat16 h2 = __float2bfloat16(v.z);
        __nv_bfloat16 h3 = __float2bfloat16(v.w);
        __nv_bfloat16 l0 = __float2bfloat16(v.x - __bfloat162float(h0));
        __nv_bfloat16 l1 = __float2bfloat16(v.y - __bfloat162float(h1));
        __nv_bfloat16 l2 = __float2bfloat16(v.z - __bfloat162float(h2));
        __nv_bfloat16 l3 = __float2bfloat16(v.w - __bfloat162float(h3));
        ((uint2*)g_xh)[i] = make_uint2(pack_bf2(h0, h1), pack_bf2(h2, h3));
        ((uint2*)g_xl)[i] = make_uint2(pack_bf2(l0, l1), pack_bf2(l2, l3));
    } else {
        int i = (b - XSPLIT_BLOCKS) * 256 + threadIdx.x;
        if (i >= T_STEPS * 128 * 64) return;
        int t = i >> 13;
        int j = (i >> 6) & 127;
        int k = i & 63;
        int kcat = k + ((j >> 6) << 6);
        float v = W[(size_t)t * 8192 + kcat * 64 + (j & 63)];
        __nv_bfloat16 h = __float2bfloat16(v);
        __nv_bfloat16 l = __float2bfloat16(v - __bfloat162float(h));
        g_wh[i] = h;
        g_wl[i] = l;
    }
}

// ---------------- tiny kernels ---------------------------------------------
__global__ void k_zero_cnt() {
    int i = blockIdx.x * blockDim.x + threadIdx.x;
    if (i < M_TOT) g_cnt[i] = 0;
}

__global__ void k_softmax(const float* __restrict__ ea) {
    if (threadIdx.x == 0) {
        float m = ea[0];
        for (int t = 1; t < T_STEPS; t++) m = fmaxf(m, ea[t]);
        float s = 0.f, e[T_STEPS];
        for (int t = 0; t < T_STEPS; t++) { e[t] = __expf(ea[t] - m); s += e[t]; }
        for (int t = 0; t < T_STEPS; t++) g_w[t] = e[t] / s;
    }
}

__global__ void k_hist(const int* __restrict__ edges) {
    int i = blockIdx.x * blockDim.x + threadIdx.x;
    if (i >= T_STEPS * EE) return;
    int t = i / EE, e = i - t * EE;
    int src = edges[(size_t)t * 2 * EE + e];
    atomicAdd(&g_cnt[t * NN + src], 1);
}

__global__ void k_scan1() {
    __shared__ int sh[256];
    int c = blockIdx.x, tid = threadIdx.x;
    int base = c * CHUNK;
    int s = 0;
    #pragma unroll
    for (int i = 0; i < CHUNK / 256; i++) {
        int idx = base + i * 256 + tid;
        if (idx < M_TOT) s += g_cnt[idx];
    }
    sh[tid] = s; __syncthreads();
    for (int off = 128; off > 0; off >>= 1) {
        if (tid < off) sh[tid] += sh[tid + off];
        __syncthreads();
    }
    if (tid == 0) g_chunksum[c] = sh[0];
}

// warp-parallel exclusive scan over NCHUNK chunk sums
__global__ void k_scan2() {
    int lane = threadIdx.x;
    int run = 0;
    for (int base = 0; base < NCHUNK; base += 32) {
        int idx = base + lane;
        int v = (idx < NCHUNK) ? g_chunksum[idx] : 0;
        int incl = v;
        #pragma unroll
        for (int off = 1; off < 32; off <<= 1) {
            int u = __shfl_up_sync(0xffffffffu, incl, off);
            if (lane >= off) incl += u;
        }
        if (idx < NCHUNK) g_chunkoff[idx] = run + incl - v;
        run += __shfl_sync(0xffffffffu, incl, 31);
    }
}

__global__ void k_scan3() {
    __shared__ int sh[256];
    int c = blockIdx.x, tid = threadIdx.x;
    const int PT = CHUNK / 256;  // 4
    int base = c * CHUNK + tid * PT;
    int v[PT];
    int s = 0;
    #pragma unroll
    for (int i = 0; i < PT; i++) {
        int idx = base + i;
        int cv = (idx < M_TOT) ? g_cnt[idx] : 0;
        v[i] = s; s += cv;
    }
    sh[tid] = s; __syncthreads();
    for (int off = 1; off < 256; off <<= 1) {
        int add = (tid >= off) ? sh[tid - off] : 0;
        __syncthreads();
        sh[tid] += add;
        __syncthreads();
    }
    int texcl = ((tid > 0) ? sh[tid - 1] : 0) + g_chunkoff[c];
    #pragma unroll
    for (int i = 0; i < PT; i++) {
        int idx = base + i;
        if (idx < M_TOT) {
            int o = texcl + v[i];
            g_rowptr[idx] = o;
            g_cursor[idx] = o;
        }
    }
}

__global__ void k_scatter(const int* __restrict__ edges) {
    int i = blockIdx.x * blockDim.x + threadIdx.x;
    if (i >= T_STEPS * EE) return;
    int t = i / EE, e = i - t * EE;
    int src = edges[(size_t)t * 2 * EE + e];
    int dst = edges[(size_t)t * 2 * EE + EE + e];
    int pos = atomicAdd(&g_cursor[t * NN + src], 1);
    g_sdst[pos] = dst;
}

// ---------------- GEMM via split-bf16 tensor cores --------------------------
#define BS 72
__global__ void __launch_bounds__(256) k_gemm() {
    extern __shared__ __nv_bfloat16 smem[];
    __nv_bfloat16* xh_s = smem;                  // [128][BS]
    __nv_bfloat16* xl_s = smem + 128 * BS;
    __nv_bfloat16* wh_s = smem + 2 * 128 * BS;   // [128 j][BS k]
    __nv_bfloat16* wl_s = smem + 3 * 128 * BS;

    int t   = blockIdx.y;
    int n0  = blockIdx.x * 128;
    int tid = threadIdx.x;

    #pragma unroll
    for (int j = 0; j < 4; j++) {
        int idx = tid + j * 256;
        int nl = idx >> 3, kq = idx & 7;
        int n = n0 + nl;
        uint4 hv = make_uint4(0, 0, 0, 0), lv = make_uint4(0, 0, 0, 0);
        if (n < NN) {
            hv = ((const uint4*)g_xh)[((size_t)n * 64 >> 3) + kq];
            lv = ((const uint4*)g_xl)[((size_t)n * 64 >> 3) + kq];
        }
        ((uint4*)xh_s)[nl * 9 + kq] = hv;
        ((uint4*)xl_s)[nl * 9 + kq] = lv;
    }
    const uint4* whg = (const uint4*)(g_wh + (size_t)t * 8192);
    const uint4* wlg = (const uint4*)(g_wl + (size_t)t * 8192);
    #pragma unroll
    for (int j = 0; j < 4; j++) {
        int idx = tid + j * 256;
        int jr = idx >> 3, kq = idx & 7;
        ((uint4*)wh_s)[jr * 9 + kq] = whg[idx];
        ((uint4*)wl_s)[jr * 9 + kq] = wlg[idx];
    }
    __syncthreads();

    int wid = tid >> 5, lane = tid & 31;
    int warp_m = wid & 3, warp_n = wid >> 2;
    int g = lane >> 2, tg = lane & 3;

    float acc[2][8][4];
    #pragma unroll
    for (int mf = 0; mf < 2; mf++)
        #pragma unroll
        for (int nf = 0; nf < 8; nf++)
            #pragma unroll
            for (int r = 0; r < 4; r++) acc[mf][nf][r] = 0.f;

    #pragma unroll
    for (int ks = 0; ks < 4; ks++) {
        int kk = ks * 16;
        uint32_t ah[2][4], al[2][4];
        #pragma unroll
        for (int mf = 0; mf < 2; mf++) {
            int r0 = warp_m * 32 + mf * 16 + g;
            int k0 = kk + 2 * tg;
            ah[mf][0] = *(const uint32_t*)&xh_s[r0 * BS + k0];
            ah[mf][1] = *(const uint32_t*)&xh_s[(r0 + 8) * BS + k0];
            ah[mf][2] = *(const uint32_t*)&xh_s[r0 * BS + k0 + 8];
            ah[mf][3] = *(const uint32_t*)&xh_s[(r0 + 8) * BS + k0 + 8];
            al[mf][0] = *(const uint32_t*)&xl_s[r0 * BS + k0];
            al[mf][1] = *(const uint32_t*)&xl_s[(r0 + 8) * BS + k0];
            al[mf][2] = *(const uint32_t*)&xl_s[r0 * BS + k0 + 8];
            al[mf][3] = *(const uint32_t*)&xl_s[(r0 + 8) * BS + k0 + 8];
        }
        #pragma unroll
        for (int nf = 0; nf < 8; nf++) {
            int col = warp_n * 64 + nf * 8 + g;
            int k0 = kk + 2 * tg;
            uint32_t bh0 = *(const uint32_t*)&wh_s[col * BS + k0];
            uint32_t bh1 = *(const uint32_t*)&wh_s[col * BS + k0 + 8];
            uint32_t bl0 = *(const uint32_t*)&wl_s[col * BS + k0];
            uint32_t bl1 = *(const uint32_t*)&wl_s[col * BS + k0 + 8];
            #pragma unroll
            for (int mf = 0; mf < 2; mf++) {
                mma_bf16(acc[mf][nf], ah[mf], bh0, bh1);
                mma_bf16(acc[mf][nf], ah[mf], bl0, bl1);
                mma_bf16(acc[mf][nf], al[mf], bh0, bh1);
            }
        }
    }

    float* dst = warp_n ? g_B : g_A;
    #pragma unroll
    for (int mf = 0; mf < 2; mf++) {
        int rb = warp_m * 32 + mf * 16;
        int nA = n0 + rb + g;
        int nB = n0 + rb + g + 8;
        #pragma unroll
        for (int nf = 0; nf < 8; nf++) {
            int jc = nf * 8 + 2 * tg;
            if (nA < NN) {
                float2 v = make_float2(acc[mf][nf][0], acc[mf][nf][1]);
                *(float2*)&dst[((size_t)t * NN + nA) * 64 + jc] = v;
            }
            if (nB < NN) {
                float2 v = make_float2(acc[mf][nf][2], acc[mf][nf][3]);
                *(float2*)&dst[((size_t)t * NN + nB) * 64 + jc] = v;
            }
        }
    }
}

// ---------------- finalize: one warp per node, prefetch all t upfront -------
__global__ void k_finalize(const float* __restrict__ bias,
                           float* __restrict__ out) {
    int gw = (blockIdx.x * blockDim.x + threadIdx.x) >> 5;
    int lane = threadIdx.x & 31;
    if (gw >= NN) return;
    int n = gw;

    int beg[T_STEPS], cnt[T_STEPS];
    #pragma unroll
    for (int t = 0; t < T_STEPS; t++) {
        int row = t * NN + n;
        beg[t] = g_rowptr[row];
        cnt[t] = g_cnt[row];
    }
    int dv[T_STEPS];
    #pragma unroll
    for (int t = 0; t < T_STEPS; t++)
        dv[t] = (lane < cnt[t]) ? g_sdst[beg[t] + lane] : 0;
    float2 av[T_STEPS];
    #pragma unroll
    for (int t = 0; t < T_STEPS; t++)
        av[t] = *(const float2*)&g_A[((size_t)(t * NN + n)) * 64 + 2 * lane];

    float ox = 0.f, oy = 0.f;

    #pragma unroll
    for (int t = 0; t < T_STEPS; t++) {
        float2 bi = *(const float2*)&bias[t * 64 + 2 * lane];
        float ax = av[t].x + bi.x, ay = av[t].y + bi.y;
        const float* Bt = g_B + (size_t)t * NN * 64;

        float sx = 0.f, sy = 0.f;
        int c = cnt[t];
        int m = min(32, c);
        int i = 0;
        for (; i + 4 <= m; i += 4) {
            int d0 = __shfl_sync(0xffffffffu, dv[t], i);
            int d1 = __shfl_sync(0xffffffffu, dv[t], i + 1);
            int d2 = __shfl_sync(0xffffffffu, dv[t], i + 2);
            int d3 = __shfl_sync(0xffffffffu, dv[t], i + 3);
            float2 b0 = *(const float2*)&Bt[(size_t)d0 * 64 + 2 * lane];
            float2 b1 = *(const float2*)&Bt[(size_t)d1 * 64 + 2 * lane];
            float2 b2 = *(const float2*)&Bt[(size_t)d2 * 64 + 2 * lane];
            float2 b3 = *(const float2*)&Bt[(size_t)d3 * 64 + 2 * lane];
            sx += fmaxf(ax + b0.x, 0.f); sy += fmaxf(ay + b0.y, 0.f);
            sx += fmaxf(ax + b1.x, 0.f); sy += fmaxf(ay + b1.y, 0.f);
            sx += fmaxf(ax + b2.x, 0.f); sy += fmaxf(ay + b2.y, 0.f);
            sx += fmaxf(ax + b3.x, 0.f); sy += fmaxf(ay + b3.y, 0.f);
        }
        for (; i < m; i++) {
            int di = __shfl_sync(0xffffffffu, dv[t], i);
            float2 bv = *(const float2*)&Bt[(size_t)di * 64 + 2 * lane];
            sx += fmaxf(ax + bv.x, 0.f);
            sy += fmaxf(ay + bv.y, 0.f);
        }
        for (int base = 32; base < c; base += 32) {
            int mm = min(32, c - base);
            int d = (lane < mm) ? g_sdst[beg[t] + base + lane] : 0;
            int ii = 0;
            for (; ii + 4 <= mm; ii += 4) {
                int d0 = __shfl_sync(0xffffffffu, d, ii);
                int d1 = __shfl_sync(0xffffffffu, d, ii + 1);
                int d2 = __shfl_sync(0xffffffffu, d, ii + 2);
                int d3 = __shfl_sync(0xffffffffu, d, ii + 3);
                float2 b0 = *(const float2*)&Bt[(size_t)d0 * 64 + 2 * lane];
                float2 b1 = *(const float2*)&Bt[(size_t)d1 * 64 + 2 * lane];
                float2 b2 = *(const float2*)&Bt[(size_t)d2 * 64 + 2 * lane];
                float2 b3 = *(const float2*)&Bt[(size_t)d3 * 64 + 2 * lane];
                sx += fmaxf(ax + b0.x, 0.f); sy += fmaxf(ay + b0.y, 0.f);
                sx += fmaxf(ax + b1.x, 0.f); sy += fmaxf(ay + b1.y, 0.f);
                sx += fmaxf(ax + b2.x, 0.f); sy += fmaxf(ay + b2.y, 0.f);
                sx += fmaxf(ax + b3.x, 0.f); sy += fmaxf(ay + b3.y, 0.f);
            }
            for (; ii < mm; ii++) {
                int di = __shfl_sync(0xffffffffu, d, ii);
                float2 bv = *(const float2*)&Bt[(size_t)di * 64 + 2 * lane];
                sx += fmaxf(ax + bv.x, 0.f);
                sy += fmaxf(ay + bv.y, 0.f);
            }
        }
        float scale = g_w[t] / (float)max(c, 1);
        ox = fmaf(scale, sx, ox);
        oy = fmaf(scale, sy, oy);
    }
    float2 o = make_float2(ox, oy);
    *(float2*)&out[(size_t)n * 64 + 2 * lane] = o;
}

// ---------------- launch: forked graph (feature chain || edge chain) --------
extern "C" void kernel_launch(void* const* d_in, const int* in_sizes, int n_in,
                              void* d_out, int out_size) {
    const float* x     = (const float*)d_in[0];  // (N, 64)
    const float* W     = (const float*)d_in[1];  // (T, 128, 64)
    const float* bias  = (const float*)d_in[2];  // (T, 64)
    const float* ea    = (const float*)d_in[3];  // (T,)
    const int*   edges = (const int*)d_in[4];    // (T, 2, E)
    float* out = (float*)d_out;

    (void)in_sizes; (void)n_in; (void)out_size;

    static cudaStream_t s2 = nullptr;
    static cudaEvent_t evFork = nullptr, evJoin = nullptr;
    static int gemm_smem = 4 * 128 * BS * sizeof(__nv_bfloat16);  // 73728 B
    if (!s2) {
        cudaStreamCreateWithFlags(&s2, cudaStreamNonBlocking);
        cudaEventCreateWithFlags(&evFork, cudaEventDisableTiming);
        cudaEventCreateWithFlags(&evJoin, cudaEventDisableTiming);
        cudaFuncSetAttribute(k_gemm, cudaFuncAttributeMaxDynamicSharedMemorySize,
                             gemm_smem);
    }

    // fork: edge chain on s2, feature chain on main stream
    cudaEventRecord(evFork, 0);
    cudaStreamWaitEvent(s2, evFork, 0);

    // ---- edge chain (s2) ----
    k_zero_cnt<<<(M_TOT + 255) / 256, 256, 0, s2>>>();
    k_hist<<<(T_STEPS * EE + 255) / 256, 256, 0, s2>>>(edges);
    k_scan1<<<NCHUNK, 256, 0, s2>>>();
    k_scan2<<<1, 32, 0, s2>>>();
    k_scan3<<<NCHUNK, 256, 0, s2>>>();
    k_scatter<<<(T_STEPS * EE + 255) / 256, 256, 0, s2>>>(edges);

    // ---- feature chain (main stream) ----
    k_softmax<<<1, 32>>>(ea);
    k_split_xw<<<XSPLIT_BLOCKS + WSPLIT_BLOCKS, 256>>>(x, W);
    dim3 ggrid((NN + 127) / 128, T_STEPS);
    k_gemm<<<ggrid, 256, gemm_smem>>>();

    // join and finalize
    cudaEventRecord(evJoin, s2);
    cudaStreamWaitEvent(0, evJoin, 0);
    k_finalize<<<(NN * 32 + 255) / 256, 256>>>(bias, out);
}

// round 11
// speedup vs baseline: 1.3911x; 1.1084x over previous
#include <cuda_runtime.h>
#include <cuda_bf16.h>
#include <cstdint>

#define T_STEPS 5
#define NN 100000
#define DD 64
#define EE 400000

#define M_TOT (T_STEPS * NN)            // 500000 (t,node) rows
#define CHUNK 1024
#define NCHUNK ((M_TOT + CHUNK - 1) / CHUNK)  // 489

// ---------------- device scratch (static globals: allocation-free) ----------
__device__ float g_A[(size_t)T_STEPS * NN * DD];   // x @ W_top  (128 MB)
__device__ float g_B[(size_t)T_STEPS * NN * DD];   // x @ W_bot  (128 MB)
__device__ __nv_bfloat16 g_xh[(size_t)NN * DD];    // x hi split
__device__ __nv_bfloat16 g_xl[(size_t)NN * DD];    // x lo split
__device__ __nv_bfloat16 g_wh[(size_t)T_STEPS * 128 * 64];  // W hi, [t][j][k]
__device__ __nv_bfloat16 g_wl[(size_t)T_STEPS * 128 * 64];  // W lo, [t][j][k]
__device__ int   g_cnt[M_TOT];
__device__ int   g_rowptr[M_TOT];
__device__ int   g_cursor[M_TOT];
__device__ int   g_sdst[(size_t)T_STEPS * EE];     // dst sorted by (t,src)
__device__ int   g_chunksum[NCHUNK];
__device__ int   g_chunkoff[NCHUNK];
__device__ float g_w[T_STEPS];

// ---------------- helpers ----------------------------------------------------
__device__ __forceinline__ uint32_t pack_bf2(__nv_bfloat16 a, __nv_bfloat16 b) {
    __nv_bfloat162 p = __halves2bfloat162(a, b);
    return *(uint32_t*)&p;
}

__device__ __forceinline__ void mma_bf16(float* c, const uint32_t* a,
                                         uint32_t b0, uint32_t b1) {
    asm("mma.sync.aligned.m16n8k16.row.col.f32.bf16.bf16.f32 "
        "{%0,%1,%2,%3}, {%4,%5,%6,%7}, {%8,%9}, {%0,%1,%2,%3};"
        : "+f"(c[0]), "+f"(c[1]), "+f"(c[2]), "+f"(c[3])
        : "r"(a[0]), "r"(a[1]), "r"(a[2]), "r"(a[3]), "r"(b0), "r"(b1));
}

// ---------------- fused split kernel (x and W halves by block range) --------
#define XSPLIT_BLOCKS 6250   // NN*DD/4 / 256
#define WSPLIT_BLOCKS 160    // T*128*64 / 256
__global__ void k_split_xw(const float* __restrict__ x,
                           const float* __restrict__ W) {
    int b = blockIdx.x;
    if (b < XSPLIT_BLOCKS) {
        int i = b * 256 + threadIdx.x;
        if (i >= NN * DD / 4) return;
        float4 v = ((const float4*)x)[i];
        __nv_bfloat16 h0 = __float2bfloat16(v.x);
        __nv_bfloat16 h1 = __float2bfloat16(v.y);
        __nv_bfloat16 h2 = __float2bfloat16(v.z);
        __nv_bfloat16 h3 = __float2bfloat16(v.w);
        __nv_bfloat16 l0 = __float2bfloat16(v.x - __bfloat162float(h0));
        __nv_bfloat16 l1 = __float2bfloat16(v.y - __bfloat162float(h1));
        __nv_bfloat16 l2 = __float2bfloat16(v.z - __bfloat162float(h2));
        __nv_bfloat16 l3 = __float2bfloat16(v.w - __bfloat162float(h3));
        ((uint2*)g_xh)[i] = make_uint2(pack_bf2(h0, h1), pack_bf2(h2, h3));
        ((uint2*)g_xl)[i] = make_uint2(pack_bf2(l0, l1), pack_bf2(l2, l3));
    } else {
        int i = (b - XSPLIT_BLOCKS) * 256 + threadIdx.x;
        if (i >= T_STEPS * 128 * 64) return;
        int t = i >> 13;
        int j = (i >> 6) & 127;
        int k = i & 63;
        int kcat = k + ((j >> 6) << 6);
        float v = W[(size_t)t * 8192 + kcat * 64 + (j & 63)];
        __nv_bfloat16 h = __float2bfloat16(v);
        __nv_bfloat16 l = __float2bfloat16(v - __bfloat162float(h));
        g_wh[i] = h;
        g_wl[i] = l;
    }
}

// ---------------- tiny kernels ---------------------------------------------
__global__ void k_zero_cnt() {
    int i = blockIdx.x * blockDim.x + threadIdx.x;
    if (i < M_TOT) g_cnt[i] = 0;
}

__global__ void k_softmax(const float* __restrict__ ea) {
    if (threadIdx.x == 0) {
        float m = ea[0];
        for (int t = 1; t < T_STEPS; t++) m = fmaxf(m, ea[t]);
        float s = 0.f, e[T_STEPS];
        for (int t = 0; t < T_STEPS; t++) { e[t] = __expf(ea[t] - m); s += e[t]; }
        for (int t = 0; t < T_STEPS; t++) g_w[t] = e[t] / s;
    }
}

__global__ void k_hist(const int* __restrict__ edges) {
    int i = blockIdx.x * blockDim.x + threadIdx.x;
    if (i >= T_STEPS * EE) return;
    int t = i / EE, e = i - t * EE;
    int src = edges[(size_t)t * 2 * EE + e];
    atomicAdd(&g_cnt[t * NN + src], 1);
}

__global__ void k_scan1() {
    __shared__ int sh[256];
    int c = blockIdx.x, tid = threadIdx.x;
    int base = c * CHUNK;
    int s = 0;
    #pragma unroll
    for (int i = 0; i < CHUNK / 256; i++) {
        int idx = base + i * 256 + tid;
        if (idx < M_TOT) s += g_cnt[idx];
    }
    sh[tid] = s; __syncthreads();
    for (int off = 128; off > 0; off >>= 1) {
        if (tid < off) sh[tid] += sh[tid + off];
        __syncthreads();
    }
    if (tid == 0) g_chunksum[c] = sh[0];
}

// single-block parallel exclusive scan over NCHUNK chunk sums (512 threads)
__global__ void k_scan2() {
    __shared__ int sh[512];
    int tid = threadIdx.x;
    int v = (tid < NCHUNK) ? g_chunksum[tid] : 0;
    sh[tid] = v; __syncthreads();
    for (int off = 1; off < 512; off <<= 1) {
        int add = (tid >= off) ? sh[tid - off] : 0;
        __syncthreads();
        sh[tid] += add;
        __syncthreads();
    }
    if (tid < NCHUNK) g_chunkoff[tid] = sh[tid] - v;
}

__global__ void k_scan3() {
    __shared__ int sh[256];
    int c = blockIdx.x, tid = threadIdx.x;
    const int PT = CHUNK / 256;  // 4
    int base = c * CHUNK + tid * PT;
    int v[PT];
    int s = 0;
    #pragma unroll
    for (int i = 0; i < PT; i++) {
        int idx = base + i;
        int cv = (idx < M_TOT) ? g_cnt[idx] : 0;
        v[i] = s; s += cv;
    }
    sh[tid] = s; __syncthreads();
    for (int off = 1; off < 256; off <<= 1) {
        int add = (tid >= off) ? sh[tid - off] : 0;
        __syncthreads();
        sh[tid] += add;
        __syncthreads();
    }
    int texcl = ((tid > 0) ? sh[tid - 1] : 0) + g_chunkoff[c];
    #pragma unroll
    for (int i = 0; i < PT; i++) {
        int idx = base + i;
        if (idx < M_TOT) {
            int o = texcl + v[i];
            g_rowptr[idx] = o;
            g_cursor[idx] = o;
        }
    }
}

__global__ void k_scatter(const int* __restrict__ edges) {
    int i = blockIdx.x * blockDim.x + threadIdx.x;
    if (i >= T_STEPS * EE) return;
    int t = i / EE, e = i - t * EE;
    int src = edges[(size_t)t * 2 * EE + e];
    int dst = edges[(size_t)t * 2 * EE + EE + e];
    int pos = atomicAdd(&g_cursor[t * NN + src], 1);
    g_sdst[pos] = dst;
}

// ---------------- GEMM via split-bf16 tensor cores --------------------------
#define BS 72
__global__ void __launch_bounds__(256) k_gemm() {
    extern __shared__ __nv_bfloat16 smem[];
    __nv_bfloat16* xh_s = smem;                  // [128][BS]
    __nv_bfloat16* xl_s = smem + 128 * BS;
    __nv_bfloat16* wh_s = smem + 2 * 128 * BS;   // [128 j][BS k]
    __nv_bfloat16* wl_s = smem + 3 * 128 * BS;

    int t   = blockIdx.y;
    int n0  = blockIdx.x * 128;
    int tid = threadIdx.x;

    #pragma unroll
    for (int j = 0; j < 4; j++) {
        int idx = tid + j * 256;
        int nl = idx >> 3, kq = idx & 7;
        int n = n0 + nl;
        uint4 hv = make_uint4(0, 0, 0, 0), lv = make_uint4(0, 0, 0, 0);
        if (n < NN) {
            hv = ((const uint4*)g_xh)[((size_t)n * 64 >> 3) + kq];
            lv = ((const uint4*)g_xl)[((size_t)n * 64 >> 3) + kq];
        }
        ((uint4*)xh_s)[nl * 9 + kq] = hv;
        ((uint4*)xl_s)[nl * 9 + kq] = lv;
    }
    const uint4* whg = (const uint4*)(g_wh + (size_t)t * 8192);
    const uint4* wlg = (const uint4*)(g_wl + (size_t)t * 8192);
    #pragma unroll
    for (int j = 0; j < 4; j++) {
        int idx = tid + j * 256;
        int jr = idx >> 3, kq = idx & 7;
        ((uint4*)wh_s)[jr * 9 + kq] = whg[idx];
        ((uint4*)wl_s)[jr * 9 + kq] = wlg[idx];
    }
    __syncthreads();

    int wid = tid >> 5, lane = tid & 31;
    int warp_m = wid & 3, warp_n = wid >> 2;
    int g = lane >> 2, tg = lane & 3;

    float acc[2][8][4];
    #pragma unroll
    for (int mf = 0; mf < 2; mf++)
        #pragma unroll
        for (int nf = 0; nf < 8; nf++)
            #pragma unroll
            for (int r = 0; r < 4; r++) acc[mf][nf][r] = 0.f;

    #pragma unroll
    for (int ks = 0; ks < 4; ks++) {
        int kk = ks * 16;
        uint32_t ah[2][4], al[2][4];
        #pragma unroll
        for (int mf = 0; mf < 2; mf++) {
            int r0 = warp_m * 32 + mf * 16 + g;
            int k0 = kk + 2 * tg;
            ah[mf][0] = *(const uint32_t*)&xh_s[r0 * BS + k0];
            ah[mf][1] = *(const uint32_t*)&xh_s[(r0 + 8) * BS + k0];
            ah[mf][2] = *(const uint32_t*)&xh_s[r0 * BS + k0 + 8];
            ah[mf][3] = *(const uint32_t*)&xh_s[(r0 + 8) * BS + k0 + 8];
            al[mf][0] = *(const uint32_t*)&xl_s[r0 * BS + k0];
            al[mf][1] = *(const uint32_t*)&xl_s[(r0 + 8) * BS + k0];
            al[mf][2] = *(const uint32_t*)&xl_s[r0 * BS + k0 + 8];
            al[mf][3] = *(const uint32_t*)&xl_s[(r0 + 8) * BS + k0 + 8];
        }
        #pragma unroll
        for (int nf = 0; nf < 8; nf++) {
            int col = warp_n * 64 + nf * 8 + g;
            int k0 = kk + 2 * tg;
            uint32_t bh0 = *(const uint32_t*)&wh_s[col * BS + k0];
            uint32_t bh1 = *(const uint32_t*)&wh_s[col * BS + k0 + 8];
            uint32_t bl0 = *(const uint32_t*)&wl_s[col * BS + k0];
            uint32_t bl1 = *(const uint32_t*)&wl_s[col * BS + k0 + 8];
            #pragma unroll
            for (int mf = 0; mf < 2; mf++) {
                mma_bf16(acc[mf][nf], ah[mf], bh0, bh1);
                mma_bf16(acc[mf][nf], ah[mf], bl0, bl1);
                mma_bf16(acc[mf][nf], al[mf], bh0, bh1);
            }
        }
    }

    float* dst = warp_n ? g_B : g_A;
    #pragma unroll
    for (int mf = 0; mf < 2; mf++) {
        int rb = warp_m * 32 + mf * 16;
        int nA = n0 + rb + g;
        int nB = n0 + rb + g + 8;
        #pragma unroll
        for (int nf = 0; nf < 8; nf++) {
            int jc = nf * 8 + 2 * tg;
            if (nA < NN) {
                float2 v = make_float2(acc[mf][nf][0], acc[mf][nf][1]);
                *(float2*)&dst[((size_t)t * NN + nA) * 64 + jc] = v;
            }
            if (nB < NN) {
                float2 v = make_float2(acc[mf][nf][2], acc[mf][nf][3]);
                *(float2*)&dst[((size_t)t * NN + nB) * 64 + jc] = v;
            }
        }
    }
}

// ---------------- finalize: one warp per node, 8-wide gather batches --------
__global__ void k_finalize(const float* __restrict__ bias,
                           float* __restrict__ out) {
    int gw = (blockIdx.x * blockDim.x + threadIdx.x) >> 5;
    int lane = threadIdx.x & 31;
    if (gw >= NN) return;
    int n = gw;

    int beg[T_STEPS], cnt[T_STEPS];
    #pragma unroll
    for (int t = 0; t < T_STEPS; t++) {
        int row = t * NN + n;
        beg[t] = g_rowptr[row];
        cnt[t] = g_cnt[row];
    }
    int dv[T_STEPS];
    #pragma unroll
    for (int t = 0; t < T_STEPS; t++)
        dv[t] = (lane < cnt[t]) ? g_sdst[beg[t] + lane] : 0;
    float2 av[T_STEPS];
    #pragma unroll
    for (int t = 0; t < T_STEPS; t++)
        av[t] = *(const float2*)&g_A[((size_t)(t * NN + n)) * 64 + 2 * lane];

    float ox = 0.f, oy = 0.f;

    #pragma unroll
    for (int t = 0; t < T_STEPS; t++) {
        float2 bi = *(const float2*)&bias[t * 64 + 2 * lane];
        float ax = av[t].x + bi.x, ay = av[t].y + bi.y;
        const float* Bt = g_B + (size_t)t * NN * 64;

        float sx = 0.f, sy = 0.f;
        int c = cnt[t];
        int m = min(32, c);
        int i = 0;
        // 8-wide batches: 8 independent gathers in flight
        for (; i + 8 <= m; i += 8) {
            float2 bv[8];
            #pragma unroll
            for (int q = 0; q < 8; q++) {
                int dq = __shfl_sync(0xffffffffu, dv[t], i + q);
                bv[q] = *(const float2*)&Bt[(size_t)dq * 64 + 2 * lane];
            }
            #pragma unroll
            for (int q = 0; q < 8; q++) {
                sx += fmaxf(ax + bv[q].x, 0.f);
                sy += fmaxf(ay + bv[q].y, 0.f);
            }
        }
        if (i + 4 <= m) {
            float2 bv[4];
            #pragma unroll
            for (int q = 0; q < 4; q++) {
                int dq = __shfl_sync(0xffffffffu, dv[t], i + q);
                bv[q] = *(const float2*)&Bt[(size_t)dq * 64 + 2 * lane];
            }
            #pragma unroll
            for (int q = 0; q < 4; q++) {
                sx += fmaxf(ax + bv[q].x, 0.f);
                sy += fmaxf(ay + bv[q].y, 0.f);
            }
            i += 4;
        }
        for (; i < m; i++) {
            int di = __shfl_sync(0xffffffffu, dv[t], i);
            float2 bv = *(const float2*)&Bt[(size_t)di * 64 + 2 * lane];
            sx += fmaxf(ax + bv.x, 0.f);
            sy += fmaxf(ay + bv.y, 0.f);
        }
        // rare tail: degree > 32
        for (int base = 32; base < c; base += 32) {
            int mm = min(32, c - base);
            int d = (lane < mm) ? g_sdst[beg[t] + base + lane] : 0;
            int ii = 0;
            for (; ii + 4 <= mm; ii += 4) {
                int d0 = __shfl_sync(0xffffffffu, d, ii);
                int d1 = __shfl_sync(0xffffffffu, d, ii + 1);
                int d2 = __shfl_sync(0xffffffffu, d, ii + 2);
                int d3 = __shfl_sync(0xffffffffu, d, ii + 3);
                float2 b0 = *(const float2*)&Bt[(size_t)d0 * 64 + 2 * lane];
                float2 b1 = *(const float2*)&Bt[(size_t)d1 * 64 + 2 * lane];
                float2 b2 = *(const float2*)&Bt[(size_t)d2 * 64 + 2 * lane];
                float2 b3 = *(const float2*)&Bt[(size_t)d3 * 64 + 2 * lane];
                sx += fmaxf(ax + b0.x, 0.f); sy += fmaxf(ay + b0.y, 0.f);
                sx += fmaxf(ax + b1.x, 0.f); sy += fmaxf(ay + b1.y, 0.f);
                sx += fmaxf(ax + b2.x, 0.f); sy += fmaxf(ay + b2.y, 0.f);
                sx += fmaxf(ax + b3.x, 0.f); sy += fmaxf(ay + b3.y, 0.f);
            }
            for (; ii < mm; ii++) {
                int di = __shfl_sync(0xffffffffu, d, ii);
                float2 bv = *(const float2*)&Bt[(size_t)di * 64 + 2 * lane];
                sx += fmaxf(ax + bv.x, 0.f);
                sy += fmaxf(ay + bv.y, 0.f);
            }
        }
        float scale = g_w[t] / (float)max(c, 1);
        ox = fmaf(scale, sx, ox);
        oy = fmaf(scale, sy, oy);
    }
    float2 o = make_float2(ox, oy);
    *(float2*)&out[(size_t)n * 64 + 2 * lane] = o;
}

// ---------------- launch: forked graph; code order puts k_gemm 4th for ncu --
extern "C" void kernel_launch(void* const* d_in, const int* in_sizes, int n_in,
                              void* d_out, int out_size) {
    const float* x     = (const float*)d_in[0];  // (N, 64)
    const float* W     = (const float*)d_in[1];  // (T, 128, 64)
    const float* bias  = (const float*)d_in[2];  // (T, 64)
    const float* ea    = (const float*)d_in[3];  // (T,)
    const int*   edges = (const int*)d_in[4];    // (T, 2, E)
    float* out = (float*)d_out;

    (void)in_sizes; (void)n_in; (void)out_size;

    static cudaStream_t s2 = nullptr;
    static cudaEvent_t evFork = nullptr, evJoin = nullptr;
    static int gemm_smem = 4 * 128 * BS * sizeof(__nv_bfloat16);  // 73728 B
    if (!s2) {
        cudaStreamCreateWithFlags(&s2, cudaStreamNonBlocking);
        cudaEventCreateWithFlags(&evFork, cudaEventDisableTiming);
        cudaEventCreateWithFlags(&evJoin, cudaEventDisableTiming);
        cudaFuncSetAttribute(k_gemm, cudaFuncAttributeMaxDynamicSharedMemorySize,
                             gemm_smem);
    }

    // fork point
    cudaEventRecord(evFork, 0);
    cudaStreamWaitEvent(s2, evFork, 0);

    // feature chain first in code order (gemm = 4th launch for ncu -s 5 -c 1)
    k_zero_cnt<<<(M_TOT + 255) / 256, 256, 0, s2>>>();      // #1 (edge, s2)
    k_softmax<<<1, 32>>>(ea);                               // #2 (feat)
    k_split_xw<<<XSPLIT_BLOCKS + WSPLIT_BLOCKS, 256>>>(x, W); // #3 (feat)
    dim3 ggrid((NN + 127) / 128, T_STEPS);
    k_gemm<<<ggrid, 256, gemm_smem>>>();                    // #4 (feat) <- ncu

    // rest of edge chain (s2, concurrent with gemm via DAG)
    k_hist<<<(T_STEPS * EE + 255) / 256, 256, 0, s2>>>(edges);
    k_scan1<<<NCHUNK, 256, 0, s2>>>();
    k_scan2<<<1, 512, 0, s2>>>();
    k_scan3<<<NCHUNK, 256, 0, s2>>>();
    k_scatter<<<(T_STEPS * EE + 255) / 256, 256, 0, s2>>>(edges);

    // join and finalize
    cudaEventRecord(evJoin, s2);
    cudaStreamWaitEvent(0, evJoin, 0);
    k_finalize<<<(NN * 32 + 255) / 256, 256>>>(bias, out);
}